// round 7
// baseline (speedup 1.0000x reference)
#include <cuda_runtime.h>
#include <cuda_fp16.h>
#include <cstdint>

// N = 100000, E = 1,600,000, F_IN = 256, F_OUT = 128
// d_in: X [N*256] f32, edge_rows [E] i32, edge_cols [E] i32, edge_vals [E] f32,
//       W [128*256] f32, b [128] f32.  d_out: [N*128] f32.

#define F_IN   256
#define F_OUT  128
#define MAX_N  100000
#define MAX_E  1600000

// -------------------- device scratch (no allocs allowed) --------------------
__device__ __half2 g_th[(size_t)MAX_N * (F_OUT / 2)];   // transformed, fp16 (25.6 MB)
__device__ int   g_counts[MAX_N];                        // zero at entry; gather re-zeros
__device__ int   g_offsets[MAX_N];
__device__ int   g_chunksums[256];
__device__ int2  g_sorted[MAX_E];
// W fp16, pre-laid-out as the smem image: 8 k-tiles x 128 rows x 80 bytes
#define WROW_B   80           // smem row stride in bytes (40 halves)
#define WTILE_B  (128 * WROW_B)  // 10240 bytes per BK=32 tile
__device__ __align__(16) unsigned char g_wimg[8 * WTILE_B];

// ============================================================================
// One-time W convert: f32 [128][256] -> fp16 padded tile images
// ============================================================================
__global__ void convert_w_kernel(const float* __restrict__ W) {
    const int t = blockIdx.x * blockDim.x + threadIdx.x;   // 8192
    if (t >= 128 * 64) return;
    const int n  = t >> 6;
    const int k4 = (t & 63) << 2;          // 0..252, multiple of 4
    const float4 v = *(const float4*)(W + (size_t)n * F_IN + k4);
    __half2 h0 = __floats2half2_rn(v.x, v.y);
    __half2 h1 = __floats2half2_rn(v.z, v.w);
    const int kt = k4 >> 5;                // tile index
    const int kh = k4 & 31;                // half index within tile
    unsigned char* dst = g_wimg + kt * WTILE_B + n * WROW_B + kh * 2;
    *(uint2*)dst = make_uint2(*reinterpret_cast<unsigned*>(&h0),
                              *reinterpret_cast<unsigned*>(&h1));
}

// ============================================================================
// Phase 1: fp16 mma.sync GEMM.  Block tile 128x128, BK=32, 256 threads,
// warp tile 64x32, m16n8k16 HMMA, ldmatrix fragments, 2-stage pipeline:
// W via cp.async from g_wimg, X via LDG f32 -> cvt -> STS (reg double buffer).
// ============================================================================
__device__ __forceinline__ void mma_f16(
    float& c0, float& c1, float& c2, float& c3,
    unsigned a0, unsigned a1, unsigned a2, unsigned a3,
    unsigned b0, unsigned b1)
{
    asm volatile(
        "mma.sync.aligned.m16n8k16.row.col.f32.f16.f16.f32 "
        "{%0,%1,%2,%3}, {%4,%5,%6,%7}, {%8,%9}, {%0,%1,%2,%3};"
        : "+f"(c0), "+f"(c1), "+f"(c2), "+f"(c3)
        : "r"(a0), "r"(a1), "r"(a2), "r"(a3), "r"(b0), "r"(b1));
}

#define LDSM_X4(r0, r1, r2, r3, addr)                                         \
    asm volatile("ldmatrix.sync.aligned.m8n8.x4.shared.b16 {%0,%1,%2,%3}, [%4];" \
        : "=r"(r0), "=r"(r1), "=r"(r2), "=r"(r3) : "r"(addr))

__global__ __launch_bounds__(256, 2) void gemm_f16_kernel(
    const float* __restrict__ X,
    const float* __restrict__ bias,
    int M)
{
    __shared__ __align__(128) unsigned char Xs[2][WTILE_B];
    __shared__ __align__(128) unsigned char Ws[2][WTILE_B];

    const int tid    = threadIdx.x;
    const int wid    = tid >> 5;
    const int lane   = tid & 31;
    const int warp_m = wid & 1;    // 2 warps x 64 rows
    const int warp_n = wid >> 1;   // 4 warps x 32 cols
    const int m0     = blockIdx.x * 128;

    const unsigned sX = (unsigned)__cvta_generic_to_shared(&Xs[0][0]);
    const unsigned sW = (unsigned)__cvta_generic_to_shared(&Ws[0][0]);

    // X loader mapping: thread -> (row, 16-half k chunk)
    const int lrow = tid >> 1;            // 0..127
    const int lkh  = (tid & 1) << 4;      // 0 or 16
    const int mrow = m0 + lrow;
    const bool mvalid = (mrow < M);
    const float* xrow = X + (size_t)(mvalid ? mrow : 0) * F_IN + lkh;
    unsigned char* xdst_row = nullptr;    // set per buffer

    // ldmatrix per-lane address offsets
    const int jj = lane >> 3, rr = lane & 7;
    // A: j0:(+0,+0) j1:(+8,+0) j2:(+0,+8) j3:(+8,+8)
    const unsigned a_off = (unsigned)((warp_m * 64 + ((jj & 1) << 3) + rr) * WROW_B
                                      + (((jj >> 1) << 3) << 1));
    // B: j0:(n+0,k+0) j1:(n+0,k+8) j2:(n+8,k+0) j3:(n+8,k+8)
    const unsigned b_off = (unsigned)((warp_n * 32 + ((jj >> 1) << 3) + rr) * WROW_B
                                      + (((jj & 1) << 3) << 1));

    float c[4][4][4];
#pragma unroll
    for (int mt = 0; mt < 4; ++mt)
#pragma unroll
        for (int nt = 0; nt < 4; ++nt)
#pragma unroll
            for (int i = 0; i < 4; ++i) c[mt][nt][i] = 0.0f;

    float xv[16];

    // ---------------- prologue: stage 0 ----------------
    {
        // W tile 0 via cp.async
#pragma unroll
        for (int cidx = tid; cidx < WTILE_B / 16; cidx += 256) {
            asm volatile("cp.async.cg.shared.global [%0], [%1], 16;"
                         :: "r"(sW + cidx * 16), "l"(g_wimg + cidx * 16));
        }
        asm volatile("cp.async.commit_group;" ::: "memory");
        // X tile 0: LDG + cvt + STS
        if (mvalid) {
            *(float4*)&xv[0]  = *(const float4*)(xrow + 0);
            *(float4*)&xv[4]  = *(const float4*)(xrow + 4);
            *(float4*)&xv[8]  = *(const float4*)(xrow + 8);
            *(float4*)&xv[12] = *(const float4*)(xrow + 12);
        } else {
#pragma unroll
            for (int i = 0; i < 16; ++i) xv[i] = 0.0f;
        }
        unsigned pk[8];
#pragma unroll
        for (int i = 0; i < 8; ++i) {
            __half2 h = __floats2half2_rn(xv[2 * i], xv[2 * i + 1]);
            pk[i] = *reinterpret_cast<unsigned*>(&h);
        }
        unsigned char* d = &Xs[0][0] + lrow * WROW_B + lkh * 2;
        *(uint4*)d        = make_uint4(pk[0], pk[1], pk[2], pk[3]);
        *(uint4*)(d + 16) = make_uint4(pk[4], pk[5], pk[6], pk[7]);
        asm volatile("cp.async.wait_group 0;" ::: "memory");
        __syncthreads();
    }

    const int NITER = F_IN / 32;   // 8
#pragma unroll
    for (int it = 0; it < NITER; ++it) {
        const int buf = it & 1;
        const int nxt = buf ^ 1;
        const unsigned xb = sX + (unsigned)buf * WTILE_B;
        const unsigned wb = sW + (unsigned)buf * WTILE_B;

        // ---- issue next-stage loads ----
        if (it + 1 < NITER) {
            const int k1 = (it + 1) * 32;
#pragma unroll
            for (int cidx = tid; cidx < WTILE_B / 16; cidx += 256) {
                asm volatile("cp.async.cg.shared.global [%0], [%1], 16;"
                             :: "r"(sW + (unsigned)nxt * WTILE_B + cidx * 16),
                                "l"(g_wimg + (it + 1) * WTILE_B + cidx * 16));
            }
            asm volatile("cp.async.commit_group;" ::: "memory");
            if (mvalid) {
                *(float4*)&xv[0]  = *(const float4*)(xrow + k1 + 0);
                *(float4*)&xv[4]  = *(const float4*)(xrow + k1 + 4);
                *(float4*)&xv[8]  = *(const float4*)(xrow + k1 + 8);
                *(float4*)&xv[12] = *(const float4*)(xrow + k1 + 12);
            }
        }

        // ---- compute on current stage: 2 k-steps of 16 ----
#pragma unroll
        for (int ks = 0; ks < 2; ++ks) {
            const unsigned kso = (unsigned)(ks << 5);   // 16 halves = 32 bytes
            unsigned b0[4], b1[4];
            {
                unsigned r0, r1, r2, r3;
                LDSM_X4(r0, r1, r2, r3, wb + b_off + kso);
                b0[0] = r0; b1[0] = r1; b0[1] = r2; b1[1] = r3;
                LDSM_X4(r0, r1, r2, r3, wb + b_off + kso + 16 * WROW_B);
                b0[2] = r0; b1[2] = r1; b0[3] = r2; b1[3] = r3;
            }
#pragma unroll
            for (int mt = 0; mt < 4; ++mt) {
                unsigned a0, a1, a2, a3;
                LDSM_X4(a0, a1, a2, a3, xb + a_off + kso + mt * 16 * WROW_B);
#pragma unroll
                for (int nt = 0; nt < 4; ++nt)
                    mma_f16(c[mt][nt][0], c[mt][nt][1], c[mt][nt][2], c[mt][nt][3],
                            a0, a1, a2, a3, b0[nt], b1[nt]);
            }
        }

        // ---- store next-stage X, wait for W, barrier ----
        if (it + 1 < NITER) {
            unsigned pk[8];
#pragma unroll
            for (int i = 0; i < 8; ++i) {
                __half2 h = __floats2half2_rn(xv[2 * i], xv[2 * i + 1]);
                pk[i] = *reinterpret_cast<unsigned*>(&h);
            }
            unsigned char* d = &Xs[nxt][0] + lrow * WROW_B + lkh * 2;
            *(uint4*)d        = make_uint4(pk[0], pk[1], pk[2], pk[3]);
            *(uint4*)(d + 16) = make_uint4(pk[4], pk[5], pk[6], pk[7]);
            asm volatile("cp.async.wait_group 0;" ::: "memory");
            __syncthreads();
        }
    }

    // ---- epilogue: bias + fp16 store to g_th ----
    const int r4 = lane >> 2, c2 = (lane & 3) << 1;
#pragma unroll
    for (int nt = 0; nt < 4; ++nt) {
        const int col = warp_n * 32 + nt * 8 + c2;
        const float bx = bias[col], by = bias[col + 1];
#pragma unroll
        for (int mt = 0; mt < 4; ++mt) {
            const int row = m0 + warp_m * 64 + mt * 16 + r4;
            if (row < M) {
                g_th[(size_t)row * (F_OUT / 2) + (col >> 1)] =
                    __floats2half2_rn(c[mt][nt][0] + bx, c[mt][nt][1] + by);
            }
            if (row + 8 < M) {
                g_th[(size_t)(row + 8) * (F_OUT / 2) + (col >> 1)] =
                    __floats2half2_rn(c[mt][nt][2] + bx, c[mt][nt][3] + by);
            }
        }
    }
}

// ============================================================================
// Phase 2: CSR build + warp-per-row gather (no float atomics)
// ============================================================================
__global__ void hist_kernel(const int* __restrict__ rows, int E) {
    int i = blockIdx.x * blockDim.x + threadIdx.x;
    if (i < E) atomicAdd(&g_counts[rows[i]], 1);
}

__global__ __launch_bounds__(1024) void scan1_kernel(int n) {
    __shared__ int wsum[32];
    const int t   = threadIdx.x;
    const int gid = blockIdx.x * 1024 + t;
    const int v   = (gid < n) ? g_counts[gid] : 0;

    int x = v;
#pragma unroll
    for (int d = 1; d < 32; d <<= 1) {
        int y = __shfl_up_sync(0xffffffffu, x, d);
        if ((t & 31) >= d) x += y;
    }
    if ((t & 31) == 31) wsum[t >> 5] = x;
    __syncthreads();
    if (t < 32) {
        int s = wsum[t];
#pragma unroll
        for (int d = 1; d < 32; d <<= 1) {
            int y = __shfl_up_sync(0xffffffffu, s, d);
            if (t >= d) s += y;
        }
        wsum[t] = s;
    }
    __syncthreads();
    const int base = (t >= 32) ? wsum[(t >> 5) - 1] : 0;
    const int incl = x + base;
    if (gid < n) g_offsets[gid] = incl - v;
    if (t == 1023) g_chunksums[blockIdx.x] = incl;
}

__global__ __launch_bounds__(128) void scan2_kernel(int nchunks) {
    __shared__ int wsum[4];
    const int t = threadIdx.x;
    const int v = (t < nchunks) ? g_chunksums[t] : 0;

    int x = v;
#pragma unroll
    for (int d = 1; d < 32; d <<= 1) {
        int y = __shfl_up_sync(0xffffffffu, x, d);
        if ((t & 31) >= d) x += y;
    }
    if ((t & 31) == 31) wsum[t >> 5] = x;
    __syncthreads();
    int base = 0;
    if ((t >> 5) > 0) base = wsum[0];
    if ((t >> 5) > 1) base += wsum[1];
    if ((t >> 5) > 2) base += wsum[2];
    if (t < nchunks) g_chunksums[t] = x + base - v;
}

__global__ void fill_kernel(const int* __restrict__ rows,
                            const int* __restrict__ cols,
                            const float* __restrict__ vals, int E) {
    int e = blockIdx.x * blockDim.x + threadIdx.x;
    if (e < E) {
        const int r = rows[e];
        const int pos = atomicAdd(&g_offsets[r], 1) + g_chunksums[r >> 10];
        g_sorted[pos] = make_int2(cols[e], __float_as_int(vals[e]));
    }
}

// one warp per output row; resets g_counts for the next graph replay
__global__ __launch_bounds__(256) void gather_kernel(float* __restrict__ out, int N) {
    const int warp = (int)((blockIdx.x * (unsigned)blockDim.x + threadIdx.x) >> 5);
    const int lane = threadIdx.x & 31;
    if (warp >= N) return;

    const int cnt = g_counts[warp];
    const int end = g_offsets[warp] + g_chunksums[warp >> 10];
    int i = end - cnt;
    if (lane == 0) g_counts[warp] = 0;

    float4 acc = make_float4(0.f, 0.f, 0.f, 0.f);

    for (; i + 1 < end; i += 2) {
        const int2 e0 = g_sorted[i];
        const int2 e1 = g_sorted[i + 1];
        const uint2 r0 = *((const uint2*)(g_th + (size_t)e0.x * (F_OUT / 2)) + lane);
        const uint2 r1 = *((const uint2*)(g_th + (size_t)e1.x * (F_OUT / 2)) + lane);
        const float v0 = __int_as_float(e0.y);
        const float v1 = __int_as_float(e1.y);

        float2 f00 = __half22float2(*(const __half2*)&r0.x);
        float2 f01 = __half22float2(*(const __half2*)&r0.y);
        acc.x = fmaf(v0, f00.x, acc.x);
        acc.y = fmaf(v0, f00.y, acc.y);
        acc.z = fmaf(v0, f01.x, acc.z);
        acc.w = fmaf(v0, f01.y, acc.w);

        float2 f10 = __half22float2(*(const __half2*)&r1.x);
        float2 f11 = __half22float2(*(const __half2*)&r1.y);
        acc.x = fmaf(v1, f10.x, acc.x);
        acc.y = fmaf(v1, f10.y, acc.y);
        acc.z = fmaf(v1, f11.x, acc.z);
        acc.w = fmaf(v1, f11.y, acc.w);
    }
    if (i < end) {
        const int2 e0 = g_sorted[i];
        const uint2 r0 = *((const uint2*)(g_th + (size_t)e0.x * (F_OUT / 2)) + lane);
        const float v0 = __int_as_float(e0.y);
        float2 f00 = __half22float2(*(const __half2*)&r0.x);
        float2 f01 = __half22float2(*(const __half2*)&r0.y);
        acc.x = fmaf(v0, f00.x, acc.x);
        acc.y = fmaf(v0, f00.y, acc.y);
        acc.z = fmaf(v0, f01.x, acc.z);
        acc.w = fmaf(v0, f01.y, acc.w);
    }

    *((float4*)(out + (size_t)warp * F_OUT) + lane) = acc;
}

// ============================================================================
// Launch  (gemm in kernel slot 4 — the slot ncu has been sampling)
// ============================================================================
extern "C" void kernel_launch(void* const* d_in, const int* in_sizes, int n_in,
                              void* d_out, int out_size)
{
    const float* X    = (const float*)d_in[0];
    const int*   er   = (const int*)  d_in[1];
    const int*   ec   = (const int*)  d_in[2];
    const float* ev   = (const float*)d_in[3];
    const float* W    = (const float*)d_in[4];
    const float* bias = (const float*)d_in[5];
    float* out = (float*)d_out;

    const int M = in_sizes[0] / F_IN;   // 100000
    const int E = in_sizes[1];          // 1600000
    const int nchunks = (M + 1023) / 1024;

    convert_w_kernel<<<32, 256>>>(W);                         // 1
    hist_kernel<<<(E + 255) / 256, 256>>>(er, E);             // 2
    scan1_kernel<<<nchunks, 1024>>>(M);                       // 3
    gemm_f16_kernel<<<(M + 127) / 128, 256>>>(X, bias, M);    // 4  <- ncu slot
    scan2_kernel<<<1, 128>>>(nchunks);                        // 5
    fill_kernel<<<(E + 255) / 256, 256>>>(er, ec, ev, E);     // 6
    const int gwarps_per_block = 256 / 32;
    gather_kernel<<<(M + gwarps_per_block - 1) / gwarps_per_block, 256>>>(out, M);  // 7
}

// round 8
// speedup vs baseline: 1.7478x; 1.7478x over previous
#include <cuda_runtime.h>
#include <cuda_fp16.h>
#include <cstdint>

// N = 100000, E = 1,600,000, F_IN = 256, F_OUT = 128
// d_in: X [N*256] f32, edge_rows [E] i32, edge_cols [E] i32, edge_vals [E] f32,
//       W [128*256] f32, b [128] f32.  d_out: [N*128] f32.

#define F_IN   256
#define F_OUT  128
#define MAX_N  100000
#define MAX_E  1600000

// -------------------- device scratch (no allocs allowed) --------------------
__device__ __half2 g_th[(size_t)MAX_N * (F_OUT / 2)];   // transformed, fp16 (25.6 MB)
__device__ int   g_counts[MAX_N];
__device__ int   g_offsets[MAX_N];
__device__ int   g_chunksums[256];
__device__ int2  g_sorted[MAX_E];
// W as tf32(rna) padded smem image: 8 k-tiles x 128 rows x 36 floats
#define XWB   (128 * 36)            // floats per operand tile (18432 B)
__device__ __align__(16) float g_wimg[8 * XWB];

// ============================================================================
// One-time W convert: f32 [128][256] -> tf32(rna) padded tile images
// ============================================================================
__device__ __forceinline__ float to_tf32(float f) {
    unsigned u;
    asm("cvt.rna.tf32.f32 %0, %1;" : "=r"(u) : "f"(f));
    return __uint_as_float(u);
}

__global__ void convert_w_kernel(const float* __restrict__ W) {
    const int t = blockIdx.x * blockDim.x + threadIdx.x;   // 8192 float4 slots
    if (t >= 128 * 64) return;
    const int n  = t >> 6;
    const int k4 = (t & 63) << 2;
    const float4 v = *(const float4*)(W + (size_t)n * F_IN + k4);
    const int kt = k4 >> 5;
    const int kc = k4 & 31;
    float4 o = make_float4(to_tf32(v.x), to_tf32(v.y), to_tf32(v.z), to_tf32(v.w));
    *(float4*)(g_wimg + (size_t)kt * XWB + n * 36 + kc) = o;
}

// ============================================================================
// Phase 1: TF32 tensor-core GEMM, 3-stage cp.async pipeline, both operands.
// Block tile 128x128, BK=32, 256 threads (8 warps), warp tile 64x32,
// mma.sync.m16n8k8. X streamed as truncated tf32; W from g_wimg (tf32-rna).
// ============================================================================
__device__ __forceinline__ void cp_async16(unsigned smem_dst, const float* gsrc, bool valid) {
    int sz = valid ? 16 : 0;
    asm volatile("cp.async.cg.shared.global [%0], [%1], 16, %2;\n"
                 :: "r"(smem_dst), "l"(gsrc), "r"(sz));
}

__device__ __forceinline__ void mma_tf32(
    float& c0, float& c1, float& c2, float& c3,
    unsigned a0, unsigned a1, unsigned a2, unsigned a3,
    unsigned b0, unsigned b1)
{
    asm volatile(
        "mma.sync.aligned.m16n8k8.row.col.f32.tf32.tf32.f32 "
        "{%0,%1,%2,%3}, {%4,%5,%6,%7}, {%8,%9}, {%0,%1,%2,%3};"
        : "+f"(c0), "+f"(c1), "+f"(c2), "+f"(c3)
        : "r"(a0), "r"(a1), "r"(a2), "r"(a3), "r"(b0), "r"(b1));
}

#define NITER 8   // F_IN / BK

__global__ __launch_bounds__(256) void gemm_tf32_kernel(
    const float* __restrict__ X,
    const float* __restrict__ bias,
    int M)
{
    extern __shared__ __align__(16) float smem[];   // [3][2][XWB]
    const unsigned sbase = (unsigned)__cvta_generic_to_shared(smem);

    const int tid    = threadIdx.x;
    const int wid    = tid >> 5;
    const int lane   = tid & 31;
    const int warp_m = wid & 1;
    const int warp_n = wid >> 1;
    const int g4     = lane >> 2;
    const int tig    = lane & 3;
    const int m0     = blockIdx.x * 128;

    // loader mapping: thread -> (row, 16-float k half)
    const int lrow = tid >> 1;           // 0..127
    const int lkb  = (tid & 1) << 4;     // 0 or 16
    const int mrow = m0 + lrow;
    const bool mvalid = (mrow < M);
    const float* xrow = X + (size_t)(mvalid ? mrow : 0) * F_IN + lkb;
    const float* wsrc = g_wimg + lrow * 36 + lkb;   // same lkb split works: 16|16 within 32
    const unsigned dst_off = (unsigned)((lrow * 36 + lkb) * 4);

    float c[4][4][4];
#pragma unroll
    for (int mt = 0; mt < 4; ++mt)
#pragma unroll
        for (int nt = 0; nt < 4; ++nt)
#pragma unroll
            for (int i = 0; i < 4; ++i) c[mt][nt][i] = 0.0f;

    // stage s buffers: X at s*2*XWB, W at s*2*XWB + XWB (floats)
#define STAGE_X(s) (sbase + (unsigned)(s) * 2u * XWB * 4u)
#define STAGE_W(s) (sbase + ((unsigned)(s) * 2u + 1u) * XWB * 4u)

    // ---- prologue: issue stages 0 and 1 as separate commit groups ----
#pragma unroll
    for (int s = 0; s < 2; ++s) {
        const int k0 = s * 32;
#pragma unroll
        for (int i = 0; i < 4; ++i)
            cp_async16(STAGE_X(s) + dst_off + i * 16, xrow + k0 + i * 4, mvalid);
#pragma unroll
        for (int i = 0; i < 4; ++i)
            cp_async16(STAGE_W(s) + dst_off + i * 16, wsrc + (size_t)s * XWB + i * 4, true);
        asm volatile("cp.async.commit_group;" ::: "memory");
    }

#pragma unroll
    for (int it = 0; it < NITER; ++it) {
        const int buf = it % 3;

        if (it == NITER - 1)
            asm volatile("cp.async.wait_group 0;" ::: "memory");
        else
            asm volatile("cp.async.wait_group 1;" ::: "memory");
        __syncthreads();

        // ---- issue stage it+2 (overwrites buffer (it-1)%3, already consumed) ----
        if (it + 2 < NITER) {
            const int s  = (it + 2) % 3;
            const int k0 = (it + 2) * 32;
#pragma unroll
            for (int i = 0; i < 4; ++i)
                cp_async16(STAGE_X(s) + dst_off + i * 16, xrow + k0 + i * 4, mvalid);
#pragma unroll
            for (int i = 0; i < 4; ++i)
                cp_async16(STAGE_W(s) + dst_off + i * 16,
                           wsrc + (size_t)(it + 2) * XWB + i * 4, true);
            asm volatile("cp.async.commit_group;" ::: "memory");
        }

        // ---- compute on buffer `buf`: 4 k-groups of 8 ----
        const float* Xb = smem + (size_t)buf * 2 * XWB;
        const float* Wb = Xb + XWB;
#pragma unroll
        for (int g = 0; g < 4; ++g) {
            const int kc = (g << 3) + tig;
            unsigned b0[4], b1[4];
#pragma unroll
            for (int nt = 0; nt < 4; ++nt) {
                const int n = warp_n * 32 + nt * 8 + g4;
                b0[nt] = __float_as_uint(Wb[n * 36 + kc]);
                b1[nt] = __float_as_uint(Wb[n * 36 + kc + 4]);
            }
#pragma unroll
            for (int mt = 0; mt < 4; ++mt) {
                const int r = warp_m * 64 + mt * 16 + g4;
                const unsigned a0 = __float_as_uint(Xb[r * 36 + kc]);
                const unsigned a1 = __float_as_uint(Xb[(r + 8) * 36 + kc]);
                const unsigned a2 = __float_as_uint(Xb[r * 36 + kc + 4]);
                const unsigned a3 = __float_as_uint(Xb[(r + 8) * 36 + kc + 4]);
#pragma unroll
                for (int nt = 0; nt < 4; ++nt)
                    mma_tf32(c[mt][nt][0], c[mt][nt][1], c[mt][nt][2], c[mt][nt][3],
                             a0, a1, a2, a3, b0[nt], b1[nt]);
            }
        }
        if (it + 2 < NITER) __syncthreads();   // protect buffer reuse ordering
    }

    // ---- epilogue: bias + fp16 store to g_th ----
#pragma unroll
    for (int nt = 0; nt < 4; ++nt) {
        const int col = warp_n * 32 + nt * 8 + tig * 2;
        const float bx = bias[col], by = bias[col + 1];
#pragma unroll
        for (int mt = 0; mt < 4; ++mt) {
            const int row = m0 + warp_m * 64 + mt * 16 + g4;
            if (row < M) {
                g_th[(size_t)row * (F_OUT / 2) + (col >> 1)] =
                    __floats2half2_rn(c[mt][nt][0] + bx, c[mt][nt][1] + by);
            }
            if (row + 8 < M) {
                g_th[(size_t)(row + 8) * (F_OUT / 2) + (col >> 1)] =
                    __floats2half2_rn(c[mt][nt][2] + bx, c[mt][nt][3] + by);
            }
        }
    }
}

// ============================================================================
// Phase 2: CSR build + warp-per-row gather (identical to the 148.6us config)
// ============================================================================
__global__ void hist_kernel(const int* __restrict__ rows, int E) {
    int i = blockIdx.x * blockDim.x + threadIdx.x;
    if (i < E) atomicAdd(&g_counts[rows[i]], 1);
}

__global__ __launch_bounds__(1024) void scan1_kernel(int n) {
    __shared__ int wsum[32];
    const int t   = threadIdx.x;
    const int gid = blockIdx.x * 1024 + t;
    const int v   = (gid < n) ? g_counts[gid] : 0;

    int x = v;
#pragma unroll
    for (int d = 1; d < 32; d <<= 1) {
        int y = __shfl_up_sync(0xffffffffu, x, d);
        if ((t & 31) >= d) x += y;
    }
    if ((t & 31) == 31) wsum[t >> 5] = x;
    __syncthreads();
    if (t < 32) {
        int s = wsum[t];
#pragma unroll
        for (int d = 1; d < 32; d <<= 1) {
            int y = __shfl_up_sync(0xffffffffu, s, d);
            if (t >= d) s += y;
        }
        wsum[t] = s;
    }
    __syncthreads();
    const int base = (t >= 32) ? wsum[(t >> 5) - 1] : 0;
    const int incl = x + base;
    if (gid < n) g_offsets[gid] = incl - v;
    if (t == 1023) g_chunksums[blockIdx.x] = incl;
}

__global__ __launch_bounds__(128) void scan2_kernel(int nchunks) {
    __shared__ int wsum[4];
    const int t = threadIdx.x;
    const int v = (t < nchunks) ? g_chunksums[t] : 0;

    int x = v;
#pragma unroll
    for (int d = 1; d < 32; d <<= 1) {
        int y = __shfl_up_sync(0xffffffffu, x, d);
        if ((t & 31) >= d) x += y;
    }
    if ((t & 31) == 31) wsum[t >> 5] = x;
    __syncthreads();
    int base = 0;
    if ((t >> 5) > 0) base = wsum[0];
    if ((t >> 5) > 1) base += wsum[1];
    if ((t >> 5) > 2) base += wsum[2];
    if (t < nchunks) g_chunksums[t] = x + base - v;
}

__global__ void fill_kernel(const int* __restrict__ rows,
                            const int* __restrict__ cols,
                            const float* __restrict__ vals, int E) {
    int e = blockIdx.x * blockDim.x + threadIdx.x;
    if (e < E) {
        const int r = rows[e];
        const int pos = atomicAdd(&g_offsets[r], 1) + g_chunksums[r >> 10];
        g_sorted[pos] = make_int2(cols[e], __float_as_int(vals[e]));
    }
}

__global__ __launch_bounds__(256) void gather_kernel(float* __restrict__ out, int N) {
    const int warp = (int)((blockIdx.x * (unsigned)blockDim.x + threadIdx.x) >> 5);
    const int lane = threadIdx.x & 31;
    if (warp >= N) return;

    const int cnt = g_counts[warp];
    const int end = g_offsets[warp] + g_chunksums[warp >> 10];
    int i = end - cnt;

    float4 acc = make_float4(0.f, 0.f, 0.f, 0.f);

    for (; i + 1 < end; i += 2) {
        const int2 e0 = g_sorted[i];
        const int2 e1 = g_sorted[i + 1];
        const uint2 r0 = *((const uint2*)(g_th + (size_t)e0.x * (F_OUT / 2)) + lane);
        const uint2 r1 = *((const uint2*)(g_th + (size_t)e1.x * (F_OUT / 2)) + lane);
        const float v0 = __int_as_float(e0.y);
        const float v1 = __int_as_float(e1.y);

        float2 f00 = __half22float2(*(const __half2*)&r0.x);
        float2 f01 = __half22float2(*(const __half2*)&r0.y);
        acc.x = fmaf(v0, f00.x, acc.x);
        acc.y = fmaf(v0, f00.y, acc.y);
        acc.z = fmaf(v0, f01.x, acc.z);
        acc.w = fmaf(v0, f01.y, acc.w);

        float2 f10 = __half22float2(*(const __half2*)&r1.x);
        float2 f11 = __half22float2(*(const __half2*)&r1.y);
        acc.x = fmaf(v1, f10.x, acc.x);
        acc.y = fmaf(v1, f10.y, acc.y);
        acc.z = fmaf(v1, f11.x, acc.z);
        acc.w = fmaf(v1, f11.y, acc.w);
    }
    if (i < end) {
        const int2 e0 = g_sorted[i];
        const uint2 r0 = *((const uint2*)(g_th + (size_t)e0.x * (F_OUT / 2)) + lane);
        const float v0 = __int_as_float(e0.y);
        float2 f00 = __half22float2(*(const __half2*)&r0.x);
        float2 f01 = __half22float2(*(const __half2*)&r0.y);
        acc.x = fmaf(v0, f00.x, acc.x);
        acc.y = fmaf(v0, f00.y, acc.y);
        acc.z = fmaf(v0, f01.x, acc.z);
        acc.w = fmaf(v0, f01.y, acc.w);
    }

    *((float4*)(out + (size_t)warp * F_OUT) + lane) = acc;
}

// ============================================================================
// Launch  (fill in kernel slot 4 -> ncu profiles it this round)
// ============================================================================
extern "C" void kernel_launch(void* const* d_in, const int* in_sizes, int n_in,
                              void* d_out, int out_size)
{
    const float* X    = (const float*)d_in[0];
    const int*   er   = (const int*)  d_in[1];
    const int*   ec   = (const int*)  d_in[2];
    const float* ev   = (const float*)d_in[3];
    const float* W    = (const float*)d_in[4];
    const float* bias = (const float*)d_in[5];
    float* out = (float*)d_out;

    const int M = in_sizes[0] / F_IN;   // 100000
    const int E = in_sizes[1];          // 1600000
    const int nchunks = (M + 1023) / 1024;
    const int GEMM_SMEM = 3 * 2 * XWB * 4;   // 110592 B

    cudaFuncSetAttribute(gemm_tf32_kernel,
                         cudaFuncAttributeMaxDynamicSharedMemorySize, GEMM_SMEM);

    void* caddr = nullptr;
    cudaGetSymbolAddress(&caddr, g_counts);
    cudaMemsetAsync(caddr, 0, (size_t)M * sizeof(int));

    hist_kernel<<<(E + 255) / 256, 256>>>(er, E);                  // 1
    scan1_kernel<<<nchunks, 1024>>>(M);                            // 2
    scan2_kernel<<<1, 128>>>(nchunks);                             // 3
    fill_kernel<<<(E + 255) / 256, 256>>>(er, ec, ev, E);          // 4 <- ncu slot
    convert_w_kernel<<<32, 256>>>(W);                              // 5
    gemm_tf32_kernel<<<(M + 127) / 128, 256, GEMM_SMEM>>>(X, bias, M);  // 6
    const int gwarps_per_block = 256 / 32;
    gather_kernel<<<(M + gwarps_per_block - 1) / gwarps_per_block, 256>>>(out, M);  // 7
}

// round 9
// speedup vs baseline: 2.0612x; 1.1793x over previous
#include <cuda_runtime.h>
#include <cuda_fp16.h>
#include <cstdint>

// N = 100000, E = 1,600,000, F_IN = 256, F_OUT = 128
// d_in: X [N*256] f32, edge_rows [E] i32, edge_cols [E] i32, edge_vals [E] f32,
//       W [128*256] f32, b [128] f32.  d_out: [N*128] f32.

#define F_IN   256
#define F_OUT  128
#define MAX_N  100000
#define MAX_E  1600000

// -------------------- device scratch (no allocs allowed) --------------------
__device__ __half2 g_th[(size_t)MAX_N * (F_OUT / 2)];   // transformed, fp16 (25.6 MB)
__device__ int   g_counts[MAX_N];
__device__ int   g_offsets[MAX_N];
__device__ int   g_chunksums[256];
__device__ int2  g_sorted[MAX_E];

// ============================================================================
// Phase 1: TF32 tensor-core GEMM, 2-stage cp.async pipeline (R5 proven-best).
// Block tile 128x128, BK=32, 256 threads (8 warps), warp tile 64x32,
// mma.sync.m16n8k8. X fed via cp.async (truncated tf32), W via LDG+cvt.rna+STS.
// ============================================================================
#define BM 128
#define BN 128
#define BK 32
#define BKP 36   // padded smem row stride (floats)

__device__ __forceinline__ float to_tf32(float f) {
    unsigned u;
    asm("cvt.rna.tf32.f32 %0, %1;" : "=r"(u) : "f"(f));
    return __uint_as_float(u);
}

__device__ __forceinline__ void cp_async16(float* smem_dst, const float* gsrc, bool valid) {
    unsigned s = (unsigned)__cvta_generic_to_shared(smem_dst);
    int sz = valid ? 16 : 0;
    asm volatile("cp.async.cg.shared.global [%0], [%1], 16, %2;\n"
                 :: "r"(s), "l"(gsrc), "r"(sz));
}

__device__ __forceinline__ void mma_tf32(
    float& c0, float& c1, float& c2, float& c3,
    unsigned a0, unsigned a1, unsigned a2, unsigned a3,
    unsigned b0, unsigned b1)
{
    asm volatile(
        "mma.sync.aligned.m16n8k8.row.col.f32.tf32.tf32.f32 "
        "{%0,%1,%2,%3}, {%4,%5,%6,%7}, {%8,%9}, {%0,%1,%2,%3};"
        : "+f"(c0), "+f"(c1), "+f"(c2), "+f"(c3)
        : "r"(a0), "r"(a1), "r"(a2), "r"(a3), "r"(b0), "r"(b1));
}

__global__ __launch_bounds__(256, 2) void gemm_tf32_kernel(
    const float* __restrict__ X,
    const float* __restrict__ W,
    const float* __restrict__ bias,
    int M)
{
    __shared__ __align__(16) float Xs[2][BM][BKP];
    __shared__ __align__(16) float Ws[2][BN][BKP];

    const int tid    = threadIdx.x;
    const int wid    = tid >> 5;
    const int lane   = tid & 31;
    const int warp_m = wid & 1;
    const int warp_n = wid >> 1;
    const int g4     = lane >> 2;
    const int tig    = lane & 3;
    const int m0     = blockIdx.x * BM;

    const int lrow = tid >> 1;
    const int lkb  = (tid & 1) << 4;
    const int mrow = m0 + lrow;
    const bool mvalid = (mrow < M);
    const float* xrow = X + (size_t)(mvalid ? mrow : 0) * F_IN + lkb;
    const float* wrow = W + (size_t)lrow * F_IN + lkb;

    float c[4][4][4];
#pragma unroll
    for (int mt = 0; mt < 4; ++mt)
#pragma unroll
        for (int nt = 0; nt < 4; ++nt)
#pragma unroll
            for (int i = 0; i < 4; ++i) c[mt][nt][i] = 0.0f;

    float wreg[16];

    // ---- prologue: stage 0 ----
#pragma unroll
    for (int i = 0; i < 4; ++i)
        cp_async16(&Xs[0][lrow][lkb + i * 4], xrow + i * 4, mvalid);
    asm volatile("cp.async.commit_group;\n" ::: "memory");
    {
        *(float4*)&wreg[0]  = *(const float4*)(wrow + 0);
        *(float4*)&wreg[4]  = *(const float4*)(wrow + 4);
        *(float4*)&wreg[8]  = *(const float4*)(wrow + 8);
        *(float4*)&wreg[12] = *(const float4*)(wrow + 12);
#pragma unroll
        for (int i = 0; i < 16; ++i) Ws[0][lrow][lkb + i] = to_tf32(wreg[i]);
    }
    asm volatile("cp.async.wait_group 0;\n" ::: "memory");
    __syncthreads();

    const int NITER = F_IN / BK;   // 8
#pragma unroll
    for (int it = 0; it < NITER; ++it) {
        const int buf = it & 1;
        const int nxt = buf ^ 1;

        if (it + 1 < NITER) {
            const int k1 = (it + 1) * BK;
#pragma unroll
            for (int i = 0; i < 4; ++i)
                cp_async16(&Xs[nxt][lrow][lkb + i * 4], xrow + k1 + i * 4, mvalid);
            asm volatile("cp.async.commit_group;\n" ::: "memory");
            *(float4*)&wreg[0]  = *(const float4*)(wrow + k1 + 0);
            *(float4*)&wreg[4]  = *(const float4*)(wrow + k1 + 4);
            *(float4*)&wreg[8]  = *(const float4*)(wrow + k1 + 8);
            *(float4*)&wreg[12] = *(const float4*)(wrow + k1 + 12);
        }

#pragma unroll
        for (int g = 0; g < 4; ++g) {
            const int kc = (g << 3) + tig;
            unsigned b0[4], b1[4];
#pragma unroll
            for (int nt = 0; nt < 4; ++nt) {
                const int n = warp_n * 32 + nt * 8 + g4;
                b0[nt] = __float_as_uint(Ws[buf][n][kc]);
                b1[nt] = __float_as_uint(Ws[buf][n][kc + 4]);
            }
#pragma unroll
            for (int mt = 0; mt < 4; ++mt) {
                const int r = warp_m * 64 + mt * 16 + g4;
                const unsigned a0 = __float_as_uint(Xs[buf][r][kc]);
                const unsigned a1 = __float_as_uint(Xs[buf][r + 8][kc]);
                const unsigned a2 = __float_as_uint(Xs[buf][r][kc + 4]);
                const unsigned a3 = __float_as_uint(Xs[buf][r + 8][kc + 4]);
#pragma unroll
                for (int nt = 0; nt < 4; ++nt)
                    mma_tf32(c[mt][nt][0], c[mt][nt][1], c[mt][nt][2], c[mt][nt][3],
                             a0, a1, a2, a3, b0[nt], b1[nt]);
            }
        }

        if (it + 1 < NITER) {
#pragma unroll
            for (int i = 0; i < 16; ++i) Ws[nxt][lrow][lkb + i] = to_tf32(wreg[i]);
            asm volatile("cp.async.wait_group 0;\n" ::: "memory");
            __syncthreads();
        }
    }

    // ---- epilogue: bias + fp16 store ----
#pragma unroll
    for (int nt = 0; nt < 4; ++nt) {
        const int col = warp_n * 32 + nt * 8 + tig * 2;
        const float bx = bias[col], by = bias[col + 1];
#pragma unroll
        for (int mt = 0; mt < 4; ++mt) {
            const int row = m0 + warp_m * 64 + mt * 16 + g4;
            if (row < M) {
                g_th[(size_t)row * (F_OUT / 2) + (col >> 1)] =
                    __floats2half2_rn(c[mt][nt][0] + bx, c[mt][nt][1] + by);
            }
            if (row + 8 < M) {
                g_th[(size_t)(row + 8) * (F_OUT / 2) + (col >> 1)] =
                    __floats2half2_rn(c[mt][nt][2] + bx, c[mt][nt][3] + by);
            }
        }
    }
}

// ============================================================================
// Phase 2: CSR build + warp-per-row gather (identical to 148.6us config)
// ============================================================================
__global__ void hist_kernel(const int* __restrict__ rows, int E) {
    int i = blockIdx.x * blockDim.x + threadIdx.x;
    if (i < E) atomicAdd(&g_counts[rows[i]], 1);
}

__global__ __launch_bounds__(1024) void scan1_kernel(int n) {
    __shared__ int wsum[32];
    const int t   = threadIdx.x;
    const int gid = blockIdx.x * 1024 + t;
    const int v   = (gid < n) ? g_counts[gid] : 0;

    int x = v;
#pragma unroll
    for (int d = 1; d < 32; d <<= 1) {
        int y = __shfl_up_sync(0xffffffffu, x, d);
        if ((t & 31) >= d) x += y;
    }
    if ((t & 31) == 31) wsum[t >> 5] = x;
    __syncthreads();
    if (t < 32) {
        int s = wsum[t];
#pragma unroll
        for (int d = 1; d < 32; d <<= 1) {
            int y = __shfl_up_sync(0xffffffffu, s, d);
            if (t >= d) s += y;
        }
        wsum[t] = s;
    }
    __syncthreads();
    const int base = (t >= 32) ? wsum[(t >> 5) - 1] : 0;
    const int incl = x + base;
    if (gid < n) g_offsets[gid] = incl - v;
    if (t == 1023) g_chunksums[blockIdx.x] = incl;
}

__global__ __launch_bounds__(128) void scan2_kernel(int nchunks) {
    __shared__ int wsum[4];
    const int t = threadIdx.x;
    const int v = (t < nchunks) ? g_chunksums[t] : 0;

    int x = v;
#pragma unroll
    for (int d = 1; d < 32; d <<= 1) {
        int y = __shfl_up_sync(0xffffffffu, x, d);
        if ((t & 31) >= d) x += y;
    }
    if ((t & 31) == 31) wsum[t >> 5] = x;
    __syncthreads();
    int base = 0;
    if ((t >> 5) > 0) base = wsum[0];
    if ((t >> 5) > 1) base += wsum[1];
    if ((t >> 5) > 2) base += wsum[2];
    if (t < nchunks) g_chunksums[t] = x + base - v;
}

__global__ void fill_kernel(const int* __restrict__ rows,
                            const int* __restrict__ cols,
                            const float* __restrict__ vals, int E) {
    int e = blockIdx.x * blockDim.x + threadIdx.x;
    if (e < E) {
        const int r = rows[e];
        const int pos = atomicAdd(&g_offsets[r], 1) + g_chunksums[r >> 10];
        g_sorted[pos] = make_int2(cols[e], __float_as_int(vals[e]));
    }
}

__global__ __launch_bounds__(256) void gather_kernel(float* __restrict__ out, int N) {
    const int warp = (int)((blockIdx.x * (unsigned)blockDim.x + threadIdx.x) >> 5);
    const int lane = threadIdx.x & 31;
    if (warp >= N) return;

    const int cnt = g_counts[warp];
    const int end = g_offsets[warp] + g_chunksums[warp >> 10];
    int i = end - cnt;

    float4 acc = make_float4(0.f, 0.f, 0.f, 0.f);

    for (; i + 1 < end; i += 2) {
        const int2 e0 = g_sorted[i];
        const int2 e1 = g_sorted[i + 1];
        const uint2 r0 = *((const uint2*)(g_th + (size_t)e0.x * (F_OUT / 2)) + lane);
        const uint2 r1 = *((const uint2*)(g_th + (size_t)e1.x * (F_OUT / 2)) + lane);
        const float v0 = __int_as_float(e0.y);
        const float v1 = __int_as_float(e1.y);

        float2 f00 = __half22float2(*(const __half2*)&r0.x);
        float2 f01 = __half22float2(*(const __half2*)&r0.y);
        acc.x = fmaf(v0, f00.x, acc.x);
        acc.y = fmaf(v0, f00.y, acc.y);
        acc.z = fmaf(v0, f01.x, acc.z);
        acc.w = fmaf(v0, f01.y, acc.w);

        float2 f10 = __half22float2(*(const __half2*)&r1.x);
        float2 f11 = __half22float2(*(const __half2*)&r1.y);
        acc.x = fmaf(v1, f10.x, acc.x);
        acc.y = fmaf(v1, f10.y, acc.y);
        acc.z = fmaf(v1, f11.x, acc.z);
        acc.w = fmaf(v1, f11.y, acc.w);
    }
    if (i < end) {
        const int2 e0 = g_sorted[i];
        const uint2 r0 = *((const uint2*)(g_th + (size_t)e0.x * (F_OUT / 2)) + lane);
        const float v0 = __int_as_float(e0.y);
        float2 f00 = __half22float2(*(const __half2*)&r0.x);
        float2 f01 = __half22float2(*(const __half2*)&r0.y);
        acc.x = fmaf(v0, f00.x, acc.x);
        acc.y = fmaf(v0, f00.y, acc.y);
        acc.z = fmaf(v0, f01.x, acc.z);
        acc.w = fmaf(v0, f01.y, acc.w);
    }

    *((float4*)(out + (size_t)warp * F_OUT) + lane) = acc;
}

// ============================================================================
// Launch: GEMM forked onto a side stream, CSR chain on the main stream,
// join before gather.  (Event fork-join is graph-capture legal.)
// ============================================================================
extern "C" void kernel_launch(void* const* d_in, const int* in_sizes, int n_in,
                              void* d_out, int out_size)
{
    const float* X    = (const float*)d_in[0];
    const int*   er   = (const int*)  d_in[1];
    const int*   ec   = (const int*)  d_in[2];
    const float* ev   = (const float*)d_in[3];
    const float* W    = (const float*)d_in[4];
    const float* bias = (const float*)d_in[5];
    float* out = (float*)d_out;

    const int M = in_sizes[0] / F_IN;   // 100000
    const int E = in_sizes[1];          // 1600000
    const int nchunks = (M + 1023) / 1024;

    // lazy one-time host resources (no device memory involved)
    static cudaStream_t s2 = nullptr;
    static cudaEvent_t  ev_fork = nullptr, ev_join = nullptr;
    if (s2 == nullptr) {
        cudaStreamCreateWithFlags(&s2, cudaStreamNonBlocking);
        cudaEventCreateWithFlags(&ev_fork, cudaEventDisableTiming);
        cudaEventCreateWithFlags(&ev_join, cudaEventDisableTiming);
    }

    void* caddr = nullptr;
    cudaGetSymbolAddress(&caddr, g_counts);

    // ---- fork: GEMM on s2, CSR chain on the default (capture) stream ----
    cudaEventRecord(ev_fork, 0);
    cudaStreamWaitEvent(s2, ev_fork, 0);

    cudaMemsetAsync(caddr, 0, (size_t)M * sizeof(int), 0);
    hist_kernel<<<(E + 255) / 256, 256, 0, 0>>>(er, E);
    scan1_kernel<<<nchunks, 1024, 0, 0>>>(M);

    gemm_tf32_kernel<<<(M + BM - 1) / BM, 256, 0, s2>>>(X, W, bias, M);

    scan2_kernel<<<1, 128, 0, 0>>>(nchunks);
    fill_kernel<<<(E + 255) / 256, 256, 0, 0>>>(er, ec, ev, E);

    // ---- join: gather needs both g_th (s2) and CSR (stream 0) ----
    cudaEventRecord(ev_join, s2);
    cudaStreamWaitEvent(0, ev_join, 0);

    const int gwarps_per_block = 256 / 32;
    gather_kernel<<<(M + gwarps_per_block - 1) / gwarps_per_block, 256, 0, 0>>>(out, M);
}